// round 3
// baseline (speedup 1.0000x reference)
#include <cuda_runtime.h>

// Problem constants
#define GAMMA 0.1f
#define TAU   0.01f
#define NN    256          // neuron count
#define MM    512          // astrocyte count
#define KK    512          // input dim
#define NN2   (NN * NN)    // 65536
#define SPLIT 16           // chunks per H row
#define CHUNK (NN2 / SPLIT) // 4096 floats per chunk

#define SETUP_BLKS 96
#define D_BLKS     8192
#define H_BLKS     8192
#define TOTAL_BLKS (SETUP_BLKS + D_BLKS + H_BLKS)

// Scratch (no allocations allowed in kernel_launch)
__device__ float g_phi[NN];           // sigmoid(x_new)
__device__ float g_part[MM * SPLIT];  // H@Phi partial sums
__device__ float g_win2[MM];          // W_in_2 @ I
__device__ int   g_done;              // setup-block completion counter
__device__ volatile int g_flag;       // phi-ready flag

__device__ __forceinline__ float warp_sum(float v) {
#pragma unroll
    for (int o = 16; o > 0; o >>= 1) v += __shfl_xor_sync(0xffffffffu, v, o);
    return v;
}

__device__ __forceinline__ float sigmoidf(float v) {
    return 1.0f / (1.0f + expf(-v));
}

// ---------------------------------------------------------------------------
// Mega-kernel: 16480 blocks x 256 threads.
//   [0, 96)        setup: x_new + phi + W_in_2@I, then release g_flag
//   [96, 8288)     W_new rows: D GEMV streamed, Hebbian applied after flag
//   [8288, 16480)  H@Phi partial sums (flag already set when these run)
// ---------------------------------------------------------------------------
__global__ void __launch_bounds__(256) kBig(
    const float* __restrict__ x,    const float* __restrict__ W,
    const float* __restrict__ Win1, const float* __restrict__ I,
    const float* __restrict__ Win2, const float* __restrict__ C,
    const float* __restrict__ D,    const float* __restrict__ z,
    const float* __restrict__ H,
    float* __restrict__ out_x, float* __restrict__ out_W) {

    __shared__ float s_vec[MM];
    __shared__ float s_red[8];
    int tid  = threadIdx.x;  // 256
    int warp = tid >> 5, lane = tid & 31;
    unsigned bid = blockIdx.x;

    if (bid < SETUP_BLKS) {
        // ================= setup: x_new, phi, win2 =================
        // s_vec[0..511] = I
        s_vec[tid]       = I[tid];
        s_vec[tid + 256] = I[tid + 256];
        const float4* sI = (const float4*)s_vec;

        if (bid < 32) {
            __shared__ float s_phi[NN];
            s_phi[tid] = sigmoidf(x[tid]);
            __syncthreads();
            int row = bid * 8 + warp;

            float a1 = 0.0f, a2 = 0.0f;
            const float* wr = W + (size_t)row * NN;
#pragma unroll
            for (int j = lane; j < NN; j += 32) a1 += wr[j] * s_phi[j];
            const float4* w1 = (const float4*)(Win1 + (size_t)row * KK);
#pragma unroll
            for (int q = 0; q < 4; q++) {
                float4 a = w1[lane + 32 * q];
                float4 b = sI[lane + 32 * q];
                a2 += a.x * b.x + a.y * b.y + a.z * b.z + a.w * b.w;
            }
            a1 = warp_sum(a1);
            a2 = warp_sum(a2);
            if (lane == 0) {
                float xn = (1.0f - GAMMA) * x[row] + GAMMA * a1 + a2;
                out_x[row] = xn;
                g_phi[row] = sigmoidf(xn);
                __threadfence();  // make phi visible device-wide
            }
        } else {
            __syncthreads();
            int row = (bid - 32) * 8 + warp;  // 0..511
            const float4* w2 = (const float4*)(Win2 + (size_t)row * KK);
            float acc = 0.0f;
#pragma unroll
            for (int q = 0; q < 4; q++) {
                float4 a = w2[lane + 32 * q];
                float4 b = sI[lane + 32 * q];
                acc += a.x * b.x + a.y * b.y + a.z * b.z + a.w * b.w;
            }
            acc = warp_sum(acc);
            if (lane == 0) {
                g_win2[row] = acc;
                __threadfence();
            }
        }
        __syncthreads();
        if (tid == 0) {
            int old = atomicAdd(&g_done, 1);
            if (old == SETUP_BLKS - 1) g_flag = 1;  // release
        }
    } else if (bid < SETUP_BLKS + D_BLKS) {
        // ================= W_new rows (D GEMV, then Hebbian) =================
        s_vec[tid]       = tanhf(z[tid]);
        s_vec[tid + 256] = tanhf(z[tid + 256]);
        __syncthreads();

        int p = (bid - SETUP_BLKS) * 8 + warp;
        const float4* dr = (const float4*)(D + (size_t)p * MM);
        const float4* ps = (const float4*)s_vec;
        float acc = 0.0f;
#pragma unroll
        for (int q = 0; q < 4; q++) {
            int idx = lane + 32 * q;       // 128 float4 per 512-float row
            float4 d = dr[idx];
            float4 s = ps[idx];
            acc += d.x * s.x + d.y * s.y + d.z * s.z + d.w * s.w;
        }
        acc = warp_sum(acc);
        if (lane == 0) {
            while (g_flag == 0) __nanosleep(64);   // nearly always already set
            __threadfence();                        // acquire
            int i = p >> 8, j = p & 255;
            float ph = g_phi[i] * g_phi[j];
            out_W[p] = (1.0f - GAMMA) * W[p] + GAMMA * (C[p] * ph + acc);
        }
    } else {
        // ================= H@Phi partial sums =================
        if (tid == 0) {
            while (g_flag == 0) __nanosleep(64);
        }
        __syncthreads();
        __threadfence();                            // acquire
        s_vec[tid] = g_phi[tid];
        __syncthreads();

        int b = bid - (SETUP_BLKS + D_BLKS);
        int c = b & (SPLIT - 1);  // chunk
        int m = b >> 4;           // row
        const float4* hr = (const float4*)(H + (size_t)m * NN2 + (size_t)c * CHUNK);

        float acc = 0.0f;
#pragma unroll
        for (int q = 0; q < 4; q++) {
            int f = tid + 256 * q;        // float4 index within chunk (0..1023)
            int p = c * CHUNK + f * 4;    // element index within row
            float4 h = hr[f];
            int i = p >> 8;
            int j = p & 255;              // multiple of 4, j+3 <= 255
            float pi = s_vec[i];
            acc += pi * (h.x * s_vec[j] + h.y * s_vec[j + 1] +
                         h.z * s_vec[j + 2] + h.w * s_vec[j + 3]);
        }
        acc = warp_sum(acc);
        if (lane == 0) s_red[warp] = acc;
        __syncthreads();
        if (tid == 0) {
            float t = 0.0f;
#pragma unroll
            for (int w = 0; w < 8; w++) t += s_red[w];
            g_part[m * SPLIT + c] = t;
        }
    }
}

// ---------------------------------------------------------------------------
// Combine: z_new[m] = (1-g*tau)*z[m] + g*tau*( F[m]*tanh(z[m])
//                      + sum_c g_part[m,c] + g_win2[m] )
// Also resets g_flag / g_done for the next graph replay.
// ---------------------------------------------------------------------------
__global__ void kZ(const float* __restrict__ z, const float* __restrict__ F,
                   float* __restrict__ out_z) {
    int m = blockIdx.x * 256 + threadIdx.x;  // 0..511
    const float4* pp = (const float4*)(g_part + m * SPLIT);
    float4 p0 = pp[0], p1 = pp[1], p2 = pp[2], p3 = pp[3];
    float acc = (p0.x + p0.y + p0.z + p0.w) + (p1.x + p1.y + p1.z + p1.w) +
                (p2.x + p2.y + p2.z + p2.w) + (p3.x + p3.y + p3.z + p3.w);
    acc += g_win2[m];
    float zm  = z[m];
    float psi = tanhf(zm);
    out_z[m] = (1.0f - GAMMA * TAU) * zm +
               (GAMMA * TAU) * (F[m] * psi + acc);
    if (m == 0) { g_flag = 0; g_done = 0; }  // reset for next replay
}

// ---------------------------------------------------------------------------
// Launch: inputs in metadata order: I, x, W, z, C, D, F, H, W_in_1, W_in_2.
// Output: concat(x_new[256], W_new[65536], z_new[512]) = 66304 floats.
// ---------------------------------------------------------------------------
extern "C" void kernel_launch(void* const* d_in, const int* in_sizes, int n_in,
                              void* d_out, int out_size) {
    const float* I    = (const float*)d_in[0];
    const float* x    = (const float*)d_in[1];
    const float* W    = (const float*)d_in[2];
    const float* z    = (const float*)d_in[3];
    const float* C    = (const float*)d_in[4];
    const float* D    = (const float*)d_in[5];
    const float* F    = (const float*)d_in[6];
    const float* H    = (const float*)d_in[7];
    const float* Win1 = (const float*)d_in[8];
    const float* Win2 = (const float*)d_in[9];

    float* out_x = (float*)d_out;            // [0, 256)
    float* out_W = out_x + NN;               // [256, 256+65536)
    float* out_z = out_W + NN2;              // [65792, 66304)

    // One mega-kernel: setup + D-stream + H-stream with flag dependency
    kBig<<<TOTAL_BLKS, 256>>>(x, W, Win1, I, Win2, C, D, z, H, out_x, out_W);

    // Tiny combine + flag reset
    kZ<<<2, 256>>>(z, F, out_z);
}

// round 4
// speedup vs baseline: 1.4156x; 1.4156x over previous
#include <cuda_runtime.h>

// Problem constants
#define GAMMA 0.1f
#define TAU   0.01f
#define NN    256          // neuron count
#define MM    512          // astrocyte count
#define KK    512          // input dim
#define NN2   (NN * NN)    // 65536
#define SPLIT 16           // chunks per H row
#define CHUNK (NN2 / SPLIT) // 4096 floats per chunk

#define H_BLKS 8192
#define D_BLKS 8192

// Scratch (no allocations allowed in kernel_launch)
__device__ float g_phi[NN];           // sigmoid(x_new)
__device__ float g_part[MM * SPLIT];  // H@Phi partial sums
__device__ float g_win2[MM];          // W_in_2 @ I
__device__ int   g_cnt[MM];           // per-row H-chunk arrival counters (self-resetting)

__device__ __forceinline__ float warp_sum(float v) {
#pragma unroll
    for (int o = 16; o > 0; o >>= 1) v += __shfl_xor_sync(0xffffffffu, v, o);
    return v;
}

__device__ __forceinline__ float sigmoidf(float v) {
    return 1.0f / (1.0f + expf(-v));
}

// ---------------------------------------------------------------------------
// Kernel A: 768 blocks x 128 threads (block-per-row for max MLP).
//   blocks [0,256)   : x_new[row] + g_phi[row]
//   blocks [256,768) : g_win2[row] = (W_in_2 @ I)[row]
// ---------------------------------------------------------------------------
__global__ void __launch_bounds__(128) kA(
    const float* __restrict__ x,    const float* __restrict__ W,
    const float* __restrict__ Win1, const float* __restrict__ I,
    const float* __restrict__ Win2, float* __restrict__ out_x) {

    __shared__ float s_I[KK];
    __shared__ float s_phi[NN];
    __shared__ float s_red[4];
    int tid  = threadIdx.x;  // 128
    int warp = tid >> 5, lane = tid & 31;

    ((float4*)s_I)[tid] = ((const float4*)I)[tid];  // 128 float4 = 512 floats
    const float4* sI = (const float4*)s_I;

    float v;
    if (blockIdx.x < 256) {
        int row = blockIdx.x;
        s_phi[tid]       = sigmoidf(x[tid]);
        s_phi[tid + 128] = sigmoidf(x[tid + 128]);
        __syncthreads();

        float a1 = 0.0f, a2 = 0.0f;
        if (tid < 64) {  // W row: 256 floats = 64 float4
            float4 w = ((const float4*)(W + (size_t)row * NN))[tid];
            float4 p = ((const float4*)s_phi)[tid];
            a1 = w.x * p.x + w.y * p.y + w.z * p.z + w.w * p.w;
        }
        {   // Win1 row: 512 floats = 128 float4
            float4 a = ((const float4*)(Win1 + (size_t)row * KK))[tid];
            float4 b = sI[tid];
            a2 = a.x * b.x + a.y * b.y + a.z * b.z + a.w * b.w;
        }
        v = GAMMA * a1 + a2;
    } else {
        __syncthreads();
        int row = blockIdx.x - 256;  // 0..511
        float4 a = ((const float4*)(Win2 + (size_t)row * KK))[tid];
        float4 b = sI[tid];
        v = a.x * b.x + a.y * b.y + a.z * b.z + a.w * b.w;
    }

    v = warp_sum(v);
    if (lane == 0) s_red[warp] = v;
    __syncthreads();
    if (tid == 0) {
        float t = s_red[0] + s_red[1] + s_red[2] + s_red[3];
        if (blockIdx.x < 256) {
            int row = blockIdx.x;
            float xn = (1.0f - GAMMA) * x[row] + t;
            out_x[row] = xn;
            g_phi[row] = sigmoidf(xn);
        } else {
            g_win2[blockIdx.x - 256] = t;
        }
    }
}

// ---------------------------------------------------------------------------
// Kernel B: 16384 blocks x 256 threads.
//   blocks [0, 8192)     : H@Phi partial sums; LAST chunk block per row also
//                          combines the 16 partials + win2 into z_new (tail).
//   blocks [8192, 16384) : W_new rows (D GEMV + Hebbian; phi from kA).
// H blocks run first so their tail combines hide under the D stream.
// ---------------------------------------------------------------------------
__global__ void __launch_bounds__(256) kB(
    const float* __restrict__ W, const float* __restrict__ C,
    const float* __restrict__ D, const float* __restrict__ z,
    const float* __restrict__ H, const float* __restrict__ F,
    float* __restrict__ out_W, float* __restrict__ out_z) {

    __shared__ float s_vec[MM];
    __shared__ float s_red[8];
    int tid  = threadIdx.x;  // 256
    int warp = tid >> 5, lane = tid & 31;
    unsigned bid = blockIdx.x;

    if (bid < H_BLKS) {
        // ================= H@Phi partial sums + tail combine =================
        s_vec[tid] = g_phi[tid];
        __syncthreads();

        int c = bid & (SPLIT - 1);  // chunk
        int m = bid >> 4;           // row
        const float4* hr = (const float4*)(H + (size_t)m * NN2 + (size_t)c * CHUNK);

        float acc = 0.0f;
#pragma unroll
        for (int q = 0; q < 4; q++) {
            int f = tid + 256 * q;        // float4 index within chunk (0..1023)
            int p = c * CHUNK + f * 4;    // element index within row
            float4 h = hr[f];
            int i = p >> 8;
            int j = p & 255;              // multiple of 4, j+3 <= 255
            float pi = s_vec[i];
            acc += pi * (h.x * s_vec[j] + h.y * s_vec[j + 1] +
                         h.z * s_vec[j + 2] + h.w * s_vec[j + 3]);
        }
        acc = warp_sum(acc);
        if (lane == 0) s_red[warp] = acc;
        __syncthreads();
        if (tid == 0) {
            float t = 0.0f;
#pragma unroll
            for (int w = 0; w < 8; w++) t += s_red[w];
            g_part[m * SPLIT + c] = t;
            __threadfence();                       // publish partial
            int old = atomicAdd(&g_cnt[m], 1);
            if (old == SPLIT - 1) {
                // last chunk of row m: combine (deterministic fixed order)
                g_cnt[m] = 0;                      // reset for next replay
                __threadfence();                   // acquire others' partials
                float s = 0.0f;
#pragma unroll
                for (int c2 = 0; c2 < SPLIT; c2++) s += g_part[m * SPLIT + c2];
                s += g_win2[m];
                float zm  = z[m];
                float psi = tanhf(zm);
                out_z[m] = (1.0f - GAMMA * TAU) * zm +
                           (GAMMA * TAU) * (F[m] * psi + s);
            }
        }
    } else {
        // ================= W_new rows (D GEMV + Hebbian) =================
        s_vec[tid]       = tanhf(z[tid]);
        s_vec[tid + 256] = tanhf(z[tid + 256]);
        __syncthreads();

        int p = (bid - H_BLKS) * 8 + warp;
        const float4* dr = (const float4*)(D + (size_t)p * MM);
        const float4* ps = (const float4*)s_vec;
        float acc = 0.0f;
#pragma unroll
        for (int q = 0; q < 4; q++) {
            int idx = lane + 32 * q;       // 128 float4 per 512-float row
            float4 d = dr[idx];
            float4 s = ps[idx];
            acc += d.x * s.x + d.y * s.y + d.z * s.z + d.w * s.w;
        }
        acc = warp_sum(acc);
        if (lane == 0) {
            int i = p >> 8, j = p & 255;
            float ph = g_phi[i] * g_phi[j];
            out_W[p] = (1.0f - GAMMA) * W[p] + GAMMA * (C[p] * ph + acc);
        }
    }
}

// ---------------------------------------------------------------------------
// Launch: inputs in metadata order: I, x, W, z, C, D, F, H, W_in_1, W_in_2.
// Output: concat(x_new[256], W_new[65536], z_new[512]) = 66304 floats.
// ---------------------------------------------------------------------------
extern "C" void kernel_launch(void* const* d_in, const int* in_sizes, int n_in,
                              void* d_out, int out_size) {
    const float* I    = (const float*)d_in[0];
    const float* x    = (const float*)d_in[1];
    const float* W    = (const float*)d_in[2];
    const float* z    = (const float*)d_in[3];
    const float* C    = (const float*)d_in[4];
    const float* D    = (const float*)d_in[5];
    const float* F    = (const float*)d_in[6];
    const float* H    = (const float*)d_in[7];
    const float* Win1 = (const float*)d_in[8];
    const float* Win2 = (const float*)d_in[9];

    float* out_x = (float*)d_out;            // [0, 256)
    float* out_W = out_x + NN;               // [256, 256+65536)
    float* out_z = out_W + NN2;              // [65792, 66304)

    // Stage 1: x_new + phi + W_in_2@I  (768 small blocks, high MLP)
    kA<<<768, 128>>>(x, W, Win1, I, Win2, out_x);

    // Stage 2: fused H-partials (+ z_new tail combine) and W_new D-stream
    kB<<<H_BLKS + D_BLKS, 256>>>(W, C, D, z, H, F, out_W, out_z);
}